// round 7
// baseline (speedup 1.0000x reference)
#include <cuda_runtime.h>

// RegLSTM, single kernel, 2-way time-chain interleaving.
// Each 16-lane group owns TWO batch elements (A, B) whose recurrences are
// interleaved in the instruction stream: B's ops issue inside A's chain
// stalls (and vice versa), attacking the measured C ~= chain + 1.8*instr
// behavior of a warp with no independent work.
// Per element, math is identical to the proven R6 kernel: lane l16 = half*8+k,
// half0 owns gates (i,g), half1 owns (f,o) + cell/h; smem h-exchange with
// parity double-buffer; single p-shfl; pre-scaled exact ex2/rcp activations;
// log-domain cell; inline head with slot ring.
// Warp = 2 groups = 4 elements. Block 128 thr = 16 elements. Grid 132.

#define B_   2098
#define T_   2048
#define L2E_ 1.4426950408889634f

__device__ __forceinline__ float ex2a(float x) {
    float r; asm("ex2.approx.f32 %0, %1;" : "=f"(r) : "f"(x)); return r;
}
__device__ __forceinline__ float rcpa(float x) {
    float r; asm("rcp.approx.f32 %0, %1;" : "=f"(r) : "f"(x)); return r;
}

// One LSTM step for one element (runs on its 16-lane group).
// half0 lanes: gxA/whA = gate i, gxB/whB = gate g; half1: f and o + state.
__device__ __forceinline__ float lstm_step(
    const float4 ha, const float4 hb, const float gxA, const float gxB,
    const float* __restrict__ whA, const float* __restrict__ whB,
    float& cl, const unsigned FULL)
{
    float aA0 = fmaf(whA[3], ha.w, fmaf(whA[2], ha.z,
                fmaf(whA[1], ha.y, fmaf(whA[0], ha.x, gxA))));
    float aA1 = fmaf(whA[7], hb.w, fmaf(whA[6], hb.z,
                fmaf(whA[5], hb.y, whA[4] * hb.x)));
    float aB0 = fmaf(whB[3], ha.w, fmaf(whB[2], ha.z,
                fmaf(whB[1], ha.y, fmaf(whB[0], ha.x, gxB))));
    float aB1 = fmaf(whB[7], hb.w, fmaf(whB[6], hb.z,
                fmaf(whB[5], hb.y, whB[4] * hb.x)));
    const float preA = aA0 + aA1;
    const float preB = aB0 + aB1;
    const float actA = rcpa(1.0f + ex2a(preA));   // sigm(i) | sigm(f)
    const float actB = rcpa(1.0f + ex2a(preB));   // (tanh(g)+1)/2 | sigm(o)
    const float gvp  = fmaf(-4.0f * L2E_, actB, 2.0f * L2E_);
    const float p    = actA * gvp;                         // half0: i*(-2L2E*tanh g)
    const float pr   = __shfl_xor_sync(FULL, p, 8, 16);    // -> half1
    cl = fmaf(actA, cl, pr);                               // half1: f*cl + p
    const float scc = rcpa(1.0f + ex2a(cl));               // (tanh(c)+1)/2
    return fmaf(actB + actB, scc, -actB);                  // half1: o*tanh(c)
}

// Regression head for one element given h (valid result on half0 lane k==slot).
__device__ __forceinline__ float head_eval(
    const float4 ha, const float4 hb, const float* __restrict__ w1s,
    const float b1s, const float w2k2, const float w2kn, const float b2v,
    const unsigned FULL)
{
    float za = fmaf(w1s[0], ha.x, fmaf(w1s[1], ha.y,
               fmaf(w1s[2], ha.z, fmaf(w1s[3], ha.w, b1s))));
    float zb = fmaf(w1s[5], hb.y, fmaf(w1s[6], hb.z,
               fmaf(w1s[7], hb.w, w1s[4] * hb.x)));
    const float sz = rcpa(1.0f + ex2a(za + zb));
    float py = fmaf(w2k2, sz, w2kn);
    py += __shfl_xor_sync(FULL, py, 1, 8);
    py += __shfl_xor_sync(FULL, py, 2, 8);
    py += __shfl_xor_sync(FULL, py, 4, 8);
    return py + b2v;
}

// x-projection for an 8-step block (24 floats in 6 float4).
__device__ __forceinline__ void compute_gx(
    const float4 q0, const float4 q1, const float4 q2,
    const float4 q3, const float4 q4, const float4 q5,
    const float wiA0, const float wiA1, const float wiA2, const float bA,
    const float wiB0, const float wiB1, const float wiB2, const float bB,
    float* __restrict__ gxA, float* __restrict__ gxB)
{
    const float xs[24] = { q0.x,q0.y,q0.z,q0.w, q1.x,q1.y,q1.z,q1.w,
                           q2.x,q2.y,q2.z,q2.w, q3.x,q3.y,q3.z,q3.w,
                           q4.x,q4.y,q4.z,q4.w, q5.x,q5.y,q5.z,q5.w };
    #pragma unroll
    for (int s = 0; s < 8; s++) {
        gxA[s] = fmaf(wiA0, xs[3*s], fmaf(wiA1, xs[3*s+1], fmaf(wiA2, xs[3*s+2], bA)));
        gxB[s] = fmaf(wiB0, xs[3*s], fmaf(wiB1, xs[3*s+1], fmaf(wiB2, xs[3*s+2], bB)));
    }
}

__global__ __launch_bounds__(128, 1) void reglstm_kernel(
    const float* __restrict__ x,      // [B, T, 3]
    const float* __restrict__ W_ih,   // [32, 3]  rows: i(0-7) f(8-15) g(16-23) o(24-31)
    const float* __restrict__ W_hh,   // [32, 8]
    const float* __restrict__ b_ih,   // [32]
    const float* __restrict__ b_hh,   // [32]
    const float* __restrict__ W1,     // [8, 8]
    const float* __restrict__ b1,     // [8]
    const float* __restrict__ W2,     // [1, 8]
    const float* __restrict__ b2,     // [1]
    float* __restrict__ out)          // [B, T]
{
    const unsigned FULL = 0xFFFFFFFFu;
    const int tid  = threadIdx.x;
    const int grp  = tid >> 4;                  // 16-lane group within block (0..7)
    const int l16  = tid & 15;
    const int half = l16 >> 3;                  // 0: gates i,g   1: gates f,o + state
    const int k    = l16 & 7;                   // hidden unit

    const int gA  = blockIdx.x * 16 + grp * 2;  // element A
    const int gB  = gA + 1;                     // element B
    const int gAc = (gA < B_) ? gA : (B_ - 1);  // clamped (pad elements)
    const int gBc = (gB < B_) ? gB : (B_ - 1);
    const bool wA = (gA < B_) && !half;         // store-enable lanes (k on half0)
    const bool wB = (gB < B_) && !half;

    // h exchange: [slot][parity][unit]; slots sA=grp*2, sB=grp*2+1
    __shared__ __align__(16) float sh[16][2][8];
    const int sA = grp * 2, sB = sA + 1;

    // ---- pre-scaled gate weights (shared by both elements) ----
    const int rowA = half ? (8 + k)  : k;          // i | f
    const int rowB = half ? (24 + k) : (16 + k);   // g | o
    const float scA = -L2E_;
    const float scB = half ? -L2E_ : (-2.0f * L2E_);
    const float wiA0 = scA * W_ih[rowA*3+0], wiA1 = scA * W_ih[rowA*3+1], wiA2 = scA * W_ih[rowA*3+2];
    const float wiB0 = scB * W_ih[rowB*3+0], wiB1 = scB * W_ih[rowB*3+1], wiB2 = scB * W_ih[rowB*3+2];
    const float bA = scA * (b_ih[rowA] + b_hh[rowA]);
    const float bB = scB * (b_ih[rowB] + b_hh[rowB]);
    float whA[8], whB[8];
    #pragma unroll
    for (int j = 0; j < 8; j++) { whA[j] = scA * W_hh[rowA*8+j]; whB[j] = scB * W_hh[rowB*8+j]; }

    // head, pre-scaled: tanh(z) = 2*rcp(1+ex2(-2L2E*z)) - 1
    float w1s[8];
    #pragma unroll
    for (int j = 0; j < 8; j++) w1s[j] = (-2.0f * L2E_) * W1[k*8+j];
    const float b1s  = (-2.0f * L2E_) * b1[k];
    const float w2k2 = 2.0f * W2[k];
    const float w2kn = -W2[k];
    const float b2v  = b2[0];

    const float4* __restrict__ xvA = (const float4*)(x + (size_t)gAc * T_ * 3);
    const float4* __restrict__ xvB = (const float4*)(x + (size_t)gBc * T_ * 3);
    float* __restrict__ orA = out + (size_t)gAc * T_;
    float* __restrict__ orB = out + (size_t)gBc * T_;

    if (half) { sh[sA][0][k] = 0.0f; sh[sB][0][k] = 0.0f; }
    __syncwarp();

    float clA = 0.0f, clB = 0.0f, ykA = 0.0f, ykB = 0.0f;

    // x double-buffer: block 0 preloaded
    float4 a0 = xvA[0], a1 = xvA[1], a2 = xvA[2], a3 = xvA[3], a4 = xvA[4], a5 = xvA[5];
    float4 e0 = xvB[0], e1 = xvB[1], e2 = xvB[2], e3 = xvB[3], e4 = xvB[4], e5 = xvB[5];

    const int NIT = T_ / 8;
    for (int it = 0; it < NIT; it++) {
        // x-projection for this 8-step block, both elements
        float gxAA[8], gxBA[8], gxAB[8], gxBB[8];
        compute_gx(a0,a1,a2,a3,a4,a5, wiA0,wiA1,wiA2,bA, wiB0,wiB1,wiB2,bB, gxAA, gxBA);
        compute_gx(e0,e1,e2,e3,e4,e5, wiA0,wiA1,wiA2,bA, wiB0,wiB1,wiB2,bB, gxAB, gxBB);

        // prefetch next block (clamped)
        const int itn = (it + 1 < NIT) ? (it + 1) : it;
        a0 = xvA[itn*6+0]; a1 = xvA[itn*6+1]; a2 = xvA[itn*6+2];
        a3 = xvA[itn*6+3]; a4 = xvA[itn*6+4]; a5 = xvA[itn*6+5];
        e0 = xvB[itn*6+0]; e1 = xvB[itn*6+1]; e2 = xvB[itn*6+2];
        e3 = xvB[itn*6+3]; e4 = xvB[itn*6+4]; e5 = xvB[itn*6+5];

        #pragma unroll
        for (int s = 0; s < 8; s++) {
            const int rp = s & 1;
            const int wp = rp ^ 1;
            // h_{t-1} for both elements (4x LDS.128 broadcast)
            const float4 hA0 = *(const float4*)&sh[sA][rp][0];
            const float4 hA1 = *(const float4*)&sh[sA][rp][4];
            const float4 hB0 = *(const float4*)&sh[sB][rp][0];
            const float4 hB1 = *(const float4*)&sh[sB][rp][4];

            // heads for step t-1 (off the recurrence chain)
            {
                const float yvA = head_eval(hA0, hA1, w1s, b1s, w2k2, w2kn, b2v, FULL);
                const float yvB = head_eval(hB0, hB1, w1s, b1s, w2k2, w2kn, b2v, FULL);
                const int slot = (s - 1) & 7;          // compile-time
                if (k == slot) { ykA = yvA; ykB = yvB; }
            }
            if (s == 0 && it > 0) {
                if (wA) orA[(it - 1) * 8 + k] = ykA;   // flush previous 8 outputs
                if (wB) orB[(it - 1) * 8 + k] = ykB;
            }

            // interleaved recurrences (independent chains A, B)
            const float hA = lstm_step(hA0, hA1, gxAA[s], gxBA[s], whA, whB, clA, FULL);
            const float hB = lstm_step(hB0, hB1, gxAB[s], gxBB[s], whA, whB, clB, FULL);

            if (half) { sh[sA][wp][k] = hA; sh[sB][wp][k] = hB; }
            __syncwarp();
        }
    }

    // epilogue: heads for t = T-1 (final h is in parity buffer 0)
    {
        const float4 hA0 = *(const float4*)&sh[sA][0][0];
        const float4 hA1 = *(const float4*)&sh[sA][0][4];
        const float4 hB0 = *(const float4*)&sh[sB][0][0];
        const float4 hB1 = *(const float4*)&sh[sB][0][4];
        const float yvA = head_eval(hA0, hA1, w1s, b1s, w2k2, w2kn, b2v, FULL);
        const float yvB = head_eval(hB0, hB1, w1s, b1s, w2k2, w2kn, b2v, FULL);
        if (k == 7) { ykA = yvA; ykB = yvB; }
        if (wA) orA[T_ - 8 + k] = ykA;
        if (wB) orB[T_ - 8 + k] = ykB;
    }
}

extern "C" void kernel_launch(void* const* d_in, const int* in_sizes, int n_in,
                              void* d_out, int out_size) {
    const float* x    = (const float*)d_in[0];
    const float* W_ih = (const float*)d_in[1];
    const float* W_hh = (const float*)d_in[2];
    const float* b_ih = (const float*)d_in[3];
    const float* b_hh = (const float*)d_in[4];
    const float* W1   = (const float*)d_in[5];
    const float* b1   = (const float*)d_in[6];
    const float* W2   = (const float*)d_in[7];
    const float* b2   = (const float*)d_in[8];
    float* out = (float*)d_out;

    // 16 elements per block (8 groups x 2 interleaved) -> 132 blocks
    const int grid = (B_ + 15) / 16;
    reglstm_kernel<<<grid, 128>>>(x, W_ih, W_hh, b_ih, b_hh, W1, b1, W2, b2, out);
}